// round 4
// baseline (speedup 1.0000x reference)
#include <cuda_runtime.h>
#include <cstdint>

// TurboQuantValue: per-row (128 elems) 4-bit min/max quantize + dequantize.
// out[i] = clip(rint((x[i]-vmin)/(vscale+1e-10)),0,15)*vscale + vmin
//
// Persistent kernel: one wave (4 CTAs/SM), grid-stride over groups of 4 rows,
// double-buffered prefetch so ~4-8 LDG.128 stay in flight per warp at all times.
// min/max via REDUX.SYNC on order-preserving uint keys.

#define WARPS_PER_BLOCK 8
#define ROWS_PER_GROUP 4
#define THREADS (WARPS_PER_BLOCK * 32)
#define BLOCKS_PER_SM 4
#define NUM_SMS 152   // GB300

// Order-preserving float<->uint key: key ascending <=> float ascending.
__device__ __forceinline__ unsigned f2key(float f) {
    unsigned u = __float_as_uint(f);
    return u ^ ((unsigned)((int)u >> 31) | 0x80000000u);
}
__device__ __forceinline__ float key2f(unsigned k) {
    unsigned u = (k & 0x80000000u) ? (k ^ 0x80000000u) : ~k;
    return __uint_as_float(u);
}

__device__ __forceinline__ float4 quant_row(float4 a) {
    float mn = fminf(fminf(a.x, a.y), fminf(a.z, a.w));
    float mx = fmaxf(fmaxf(a.x, a.y), fmaxf(a.z, a.w));

    unsigned kmn = __reduce_min_sync(0xFFFFFFFFu, f2key(mn));
    unsigned kmx = __reduce_max_sync(0xFFFFFFFFu, f2key(mx));
    mn = key2f(kmn);
    mx = key2f(kmx);

    float vscale = (mx - mn) / (15.0f + 1e-10f);
    float inv    = 1.0f / (vscale + 1e-10f);
    float nb     = -mn * inv;

    float4 r;
    float q;
    q = fminf(fmaxf(rintf(fmaf(a.x, inv, nb)), 0.0f), 15.0f);
    r.x = fmaf(q, vscale, mn);
    q = fminf(fmaxf(rintf(fmaf(a.y, inv, nb)), 0.0f), 15.0f);
    r.y = fmaf(q, vscale, mn);
    q = fminf(fmaxf(rintf(fmaf(a.z, inv, nb)), 0.0f), 15.0f);
    r.z = fmaf(q, vscale, mn);
    q = fminf(fmaxf(rintf(fmaf(a.w, inv, nb)), 0.0f), 15.0f);
    r.w = fmaf(q, vscale, mn);
    return r;
}

__global__ __launch_bounds__(THREADS)
void turboquant_kernel(const float4* __restrict__ in,
                       float4* __restrict__ out,
                       int n_groups)   // groups of 4 rows; 128 float4 per group
{
    int wid  = threadIdx.x >> 5;
    int lane = threadIdx.x & 31;
    int warp_global = blockIdx.x * WARPS_PER_BLOCK + wid;
    int n_warps = gridDim.x * WARPS_PER_BLOCK;

    int g = warp_global;
    if (g >= n_groups) return;

    size_t idx = (size_t)g * 128 + lane;

    // prime: front-batch 4 streaming loads
    float4 a = __ldcs(&in[idx]);
    float4 b = __ldcs(&in[idx + 32]);
    float4 c = __ldcs(&in[idx + 64]);
    float4 d = __ldcs(&in[idx + 96]);

    for (;;) {
        int gn = g + n_warps;
        bool has_next = gn < n_groups;
        size_t idxn = (size_t)gn * 128 + lane;

        // prefetch next group (warp-uniform branch) — loads issue before the
        // current group's dependent compute/stores, keeping DRAM pipe fed
        float4 a2, b2, c2, d2;
        if (has_next) {
            a2 = __ldcs(&in[idxn]);
            b2 = __ldcs(&in[idxn + 32]);
            c2 = __ldcs(&in[idxn + 64]);
            d2 = __ldcs(&in[idxn + 96]);
        }

        // compute+store current group, row by row (caps live registers)
        __stcs(&out[idx],      quant_row(a));
        __stcs(&out[idx + 32], quant_row(b));
        __stcs(&out[idx + 64], quant_row(c));
        __stcs(&out[idx + 96], quant_row(d));

        if (!has_next) break;
        a = a2; b = b2; c = c2; d = d2;
        g = gn; idx = idxn;
    }
}

extern "C" void kernel_launch(void* const* d_in, const int* in_sizes, int n_in,
                              void* d_out, int out_size)
{
    const float4* x = (const float4*)d_in[0];
    float4* out = (float4*)d_out;

    int n_elems = in_sizes[0];                    // 67,108,864
    int n_rows = n_elems / 128;                   // 524,288
    int n_groups = n_rows / ROWS_PER_GROUP;       // 131,072

    int blocks = NUM_SMS * BLOCKS_PER_SM;         // 608 — single wave
    turboquant_kernel<<<blocks, THREADS>>>(x, out, n_groups);
}

// round 5
// speedup vs baseline: 1.1077x; 1.1077x over previous
#include <cuda_runtime.h>
#include <cstdint>

// TurboQuantValue: per-row (128 elems) 4-bit min/max quantize + dequantize.
// out[i] = clip(rint((x[i]-vmin)/(vscale+1e-10)),0,15)*vscale + vmin
// vscale = (vmax-vmin)/(15+1e-10)
//
// R2 structure (best measured): one warp = TWO rows, MLP=2, regs<=32,
// high occupancy. Plus streaming cache hints (.cs) — one-pass 512MB stream.
// min/max via REDUX.SYNC on order-preserving uint keys.

#define WARPS_PER_BLOCK 8
#define ROWS_PER_WARP 2
#define THREADS (WARPS_PER_BLOCK * 32)

// Order-preserving float<->uint key: key ascending <=> float ascending.
__device__ __forceinline__ unsigned f2key(float f) {
    unsigned u = __float_as_uint(f);
    return u ^ ((unsigned)((int)u >> 31) | 0x80000000u);
}
__device__ __forceinline__ float key2f(unsigned k) {
    unsigned u = (k & 0x80000000u) ? (k ^ 0x80000000u) : ~k;
    return __uint_as_float(u);
}

__device__ __forceinline__ float4 quant_row(float4 a) {
    float mn = fminf(fminf(a.x, a.y), fminf(a.z, a.w));
    float mx = fmaxf(fmaxf(a.x, a.y), fmaxf(a.z, a.w));

    unsigned kmn = __reduce_min_sync(0xFFFFFFFFu, f2key(mn));
    unsigned kmx = __reduce_max_sync(0xFFFFFFFFu, f2key(mx));
    mn = key2f(kmn);
    mx = key2f(kmx);

    float vscale = (mx - mn) / (15.0f + 1e-10f);
    float inv    = 1.0f / (vscale + 1e-10f);   // one IEEE div per row per lane
    float nb     = -mn * inv;

    float4 r;
    float q;
    q = fminf(fmaxf(rintf(fmaf(a.x, inv, nb)), 0.0f), 15.0f);
    r.x = fmaf(q, vscale, mn);
    q = fminf(fmaxf(rintf(fmaf(a.y, inv, nb)), 0.0f), 15.0f);
    r.y = fmaf(q, vscale, mn);
    q = fminf(fmaxf(rintf(fmaf(a.z, inv, nb)), 0.0f), 15.0f);
    r.z = fmaf(q, vscale, mn);
    q = fminf(fmaxf(rintf(fmaf(a.w, inv, nb)), 0.0f), 15.0f);
    r.w = fmaf(q, vscale, mn);
    return r;
}

__global__ __launch_bounds__(THREADS, 8)   // cap regs at 32 -> full occupancy
void turboquant_kernel(const float4* __restrict__ in,
                       float4* __restrict__ out,
                       int n_rows)
{
    int warp_in_block = threadIdx.x >> 5;
    int lane = threadIdx.x & 31;
    int row0 = (blockIdx.x * WARPS_PER_BLOCK + warp_in_block) * ROWS_PER_WARP;
    if (row0 >= n_rows) return;

    size_t idx0 = (size_t)row0 * 32 + lane;   // 32 float4 per row

    // front-load both rows (independent streaming LDG.128s, MLP=2)
    float4 a = __ldcs(&in[idx0]);
    float4 b = __ldcs(&in[idx0 + 32]);

    float4 ra = quant_row(a);
    float4 rb = quant_row(b);

    __stcs(&out[idx0],      ra);
    __stcs(&out[idx0 + 32], rb);
}

extern "C" void kernel_launch(void* const* d_in, const int* in_sizes, int n_in,
                              void* d_out, int out_size)
{
    const float4* x = (const float4*)d_in[0];
    float4* out = (float4*)d_out;

    int n_elems = in_sizes[0];          // 67,108,864
    int n_rows = n_elems / 128;         // 524,288

    int rows_per_block = WARPS_PER_BLOCK * ROWS_PER_WARP;
    int blocks = (n_rows + rows_per_block - 1) / rows_per_block;
    turboquant_kernel<<<blocks, THREADS>>>(x, out, n_rows);
}